// round 14
// baseline (speedup 1.0000x reference)
#include <cuda_runtime.h>
#include <cuda_fp16.h>
#include <cstdint>

#define NN 100000
#define NE 1600000
#define C 128
#define C3 384
#define NLAYERS 3
#define SCAN_B 512
#define SCAN_NB ((NN + SCAN_B - 1) / SCAN_B)   // 196

// padded tile layout: [rows][68 uint32 words] (64 used = 128 fp16, +4 pad)
#define TSTR 68
#define TILE_WORDS (128 * TSTR)       // B tiles: 128 n-rows  (34816 B)
#define NROW 64                       // fused-kernel CTA rows
#define A_WORDS (NROW * TSTR)         // A tiles: 64 rows     (17408 B)

// P1 role grid split
#define NB_COUNT 6250
#define NB_INIT  25000
#define NB_WF    576
// P2 role grid split
#define NB_FILL  6250
#define NB_PREPB 384

// ================= scratch (device globals; no allocation allowed) =================
__device__ __align__(256) uint32_t g_hA[NN * 64];        // hidden state ping (fp16 half2)
__device__ __align__(256) uint32_t g_hB[NN * 64];        // hidden state pong
__device__ __align__(256) float    g_wfused[3 * 128 * 384];  // W_l @ w_ih^T (fp32)
// fp16 padded B tiles: 0-8 = Wfused (layer*3+chunk), 9-11 = w_hh chunks
__device__ __align__(256) uint32_t g_btile[12 * TILE_WORDS];
// CSR build
__device__ __align__(256) int g_deg[NN];
__device__ __align__(256) int g_bsum[SCAN_NB];
__device__ __align__(256) int g_rowptr[NN + 1];
__device__ __align__(256) int g_cur[NN];
__device__ __align__(256) int g_srclist[NE];

// ================= helpers =================
__device__ __forceinline__ uint32_t smem_to_u32(const void* p) {
    uint32_t a;
    asm("{ .reg .u64 t; cvta.to.shared.u64 t, %1; cvt.u32.u64 %0, t; }" : "=r"(a) : "l"(p));
    return a;
}
__device__ __forceinline__ void cp_async16(uint32_t saddr, const void* gaddr) {
    asm volatile("cp.async.cg.shared.global [%0], [%1], 16;" :: "r"(saddr), "l"(gaddr));
}
#define CP_COMMIT() asm volatile("cp.async.commit_group;" ::: "memory")
#define CP_WAIT0()  asm volatile("cp.async.wait_group 0;" ::: "memory")

__device__ __forceinline__ uint32_t pack_h2(float a, float b) {
    __half2 h = __floats2half2_rn(a, b);
    return *(uint32_t*)&h;
}
__device__ __forceinline__ void ldmx4(uint32_t* r, uint32_t saddr) {
    asm volatile("ldmatrix.sync.aligned.m8n8.x4.shared.b16 {%0,%1,%2,%3}, [%4];"
                 : "=r"(r[0]), "=r"(r[1]), "=r"(r[2]), "=r"(r[3]) : "r"(saddr));
}
__device__ __forceinline__ float tanh_ap(float x) {
    float y;
    asm("tanh.approx.f32 %0, %1;" : "=f"(y) : "f"(x));
    return y;
}
__device__ __forceinline__ float sigmoid_ap(float x) {
    return fmaf(tanh_ap(0.5f * x), 0.5f, 0.5f);
}

// per-block edge dtype detection (thread 0 + smem broadcast)
__device__ __forceinline__ int detect_block(const unsigned int* ei32, int* s_flag) {
    if (threadIdx.x == 0) {
        int is64 = 1;
        for (int i = 1; i < 64; i += 2)
            if (ei32[i] != 0u) { is64 = 0; break; }
        *s_flag = is64;
    }
    __syncthreads();
    return *s_flag;
}
__device__ __forceinline__ int load_edge_f(const void* ei, long long idx, int is64) {
    int v;
    if (is64) v = (int)((const long long*)ei)[idx];
    else      v = ((const int*)ei)[idx];
    return min(max(v, 0), NN - 1);
}

// ================= P0: zero degree array =================
__global__ void zero_deg_kernel() {
    int i = blockIdx.x * blockDim.x + threadIdx.x;
    if (i < NN) g_deg[i] = 0;
}

// ================= P1: count + init_h + wfused (one grid, role by block) =========
__global__ void prep1_kernel(const void* __restrict__ ei, const float* __restrict__ x,
                             const float* __restrict__ weight, const float* __restrict__ w_ih) {
    __shared__ int s_flag;
    int b = blockIdx.x;
    if (b < NB_COUNT) {
        int is64 = detect_block((const unsigned int*)ei, &s_flag);
        int e = b * 256 + threadIdx.x;
        if (e < NE) atomicAdd(&g_deg[load_edge_f(ei, (long long)NE + e, is64)], 1);
    } else if (b < NB_COUNT + NB_INIT) {
        int i = (b - NB_COUNT) * 256 + threadIdx.x;
        if (i < NN * 64) {
            float2 v = ((const float2*)x)[i];
            g_hA[i] = pack_h2(v.x, v.y);
        }
    } else {
        int idx = (b - NB_COUNT - NB_INIT) * 256 + threadIdx.x;
        if (idx < 3 * 128 * 384) {
            int l = idx / 49152;
            int rem = idx % 49152;
            int k = rem / 384;
            int n = rem % 384;
            const float* wl = weight + l * 16384 + k * 128;
            const float* wr = w_ih + (size_t)n * 128;
            float s = 0.f;
#pragma unroll 8
            for (int j = 0; j < 128; j++) s += wl[j] * wr[j];
            g_wfused[idx] = s;
        }
    }
}

// ================= scans =================
__global__ void scanA_kernel() {
    __shared__ int sh[SCAN_B];
    int i = blockIdx.x * SCAN_B + threadIdx.x;
    sh[threadIdx.x] = (i < NN) ? g_deg[i] : 0;
    __syncthreads();
    for (int off = SCAN_B / 2; off > 0; off >>= 1) {
        if (threadIdx.x < off) sh[threadIdx.x] += sh[threadIdx.x + off];
        __syncthreads();
    }
    if (threadIdx.x == 0) g_bsum[blockIdx.x] = sh[0];
}
__global__ void scanB_kernel() {      // parallel exclusive scan of 196 block sums
    __shared__ int sh[256];
    int t = threadIdx.x;
    int v = (t < SCAN_NB) ? g_bsum[t] : 0;
    sh[t] = v;
    __syncthreads();
    for (int off = 1; off < 256; off <<= 1) {
        int tv = (t >= off) ? sh[t - off] : 0;
        __syncthreads();
        sh[t] += tv;
        __syncthreads();
    }
    if (t < SCAN_NB) g_bsum[t] = sh[t] - v;   // inclusive -> exclusive
}
__global__ void scanC_kernel() {
    __shared__ int sh[SCAN_B];
    int i = blockIdx.x * SCAN_B + threadIdx.x;
    int v = (i < NN) ? g_deg[i] : 0;
    sh[threadIdx.x] = v;
    __syncthreads();
    for (int off = 1; off < SCAN_B; off <<= 1) {
        int t = (threadIdx.x >= off) ? sh[threadIdx.x - off] : 0;
        __syncthreads();
        sh[threadIdx.x] += t;
        __syncthreads();
    }
    if (i < NN) {
        int excl = sh[threadIdx.x] - v + g_bsum[blockIdx.x];
        g_rowptr[i] = excl;
        g_cur[i] = excl;
    }
    if (i == NN - 1) g_rowptr[NN] = NE;
}

// ================= P2: fill + prep_btiles (one grid) =================
__global__ void prep2_kernel(const void* __restrict__ ei, const float* __restrict__ w_hh) {
    __shared__ int s_flag;
    int b = blockIdx.x;
    if (b < NB_FILL) {
        int is64 = detect_block((const unsigned int*)ei, &s_flag);
        int e = b * 256 + threadIdx.x;
        if (e < NE) {
            int src = load_edge_f(ei, e, is64);
            int dst = load_edge_f(ei, (long long)NE + e, is64);
            int pos = atomicAdd(&g_cur[dst], 1);
            if (pos >= 0 && pos < NE) g_srclist[pos] = src;
        }
    } else {
        int idx = (b - NB_FILL) * 256 + threadIdx.x;
        if (idx < 12 * 128 * 64) {
            int tile = idx >> 13;
            int rem  = idx & 8191;
            int n  = rem >> 6;
            int k2 = rem & 63;
            float v0, v1;
            if (tile < 9) {
                int l = tile / 3, chunk = tile % 3;
                const float* base = g_wfused + l * 49152 + chunk * 128 + n;
                v0 = base[(k2 * 2) * 384];
                v1 = base[(k2 * 2 + 1) * 384];
            } else {
                const float* r = w_hh + ((size_t)((tile - 9) * 128 + n)) * 128;
                v0 = r[k2 * 2];  v1 = r[k2 * 2 + 1];
            }
            g_btile[(size_t)tile * TILE_WORDS + n * TSTR + k2] = pack_h2(v0, v1);
        }
    }
}

// ================= mma.sync m16n8k16 fp16 =================
__device__ __forceinline__ void mma16816(float* c, const uint32_t* a, const uint32_t* b) {
    asm volatile(
        "mma.sync.aligned.m16n8k16.row.col.f32.f16.f16.f32 "
        "{%0,%1,%2,%3}, {%4,%5,%6,%7}, {%8,%9}, {%0,%1,%2,%3};"
        : "+f"(c[0]), "+f"(c[1]), "+f"(c[2]), "+f"(c[3])
        : "r"(a[0]), "r"(a[1]), "r"(a[2]), "r"(a[3]), "r"(b[0]), "r"(b[1]));
}

__device__ __forceinline__ void gemm_frag(uint32_t aAddr, uint32_t bAddr, float acc[8][4]) {
#pragma unroll
    for (int ks = 0; ks < 8; ks++) {
        uint32_t a[4];
        ldmx4(a, aAddr + ks * 32);
#pragma unroll
        for (int p = 0; p < 4; p++) {
            uint32_t b[4];
            ldmx4(b, bAddr + p * (16 * TSTR * 4) + ks * 32);
            mma16816(acc[2 * p],     a, b);
            mma16816(acc[2 * p + 1], a, b + 2);
        }
    }
}

// ================= fused gather + gi-GEMM + gh-GEMM + GRU gate =================
#define FUSED_SMEM ((2 * A_WORDS + 2 * TILE_WORDS) * 4)   // 104448 B, 2 CTAs/SM

__device__ __forceinline__ void prefetch_chunk(uint32_t sB, int layer, int chunk, int tid) {
    const uint32_t* srcI = g_btile + (size_t)(layer * 3 + chunk) * TILE_WORDS;
    const uint32_t* srcH = g_btile + (size_t)(9 + chunk) * TILE_WORDS;
    for (int i = tid * 4; i < TILE_WORDS; i += 256 * 4) {
        cp_async16(sB + i * 4, srcI + i);
        cp_async16(sB + (TILE_WORDS + i) * 4, srcH + i);
    }
    CP_COMMIT();
}

__global__ void __launch_bounds__(256, 2)
fused_kernel(int layer, const float* __restrict__ bias_i, const float* __restrict__ bias_h)
{
    extern __shared__ uint32_t sm[];
    uint32_t* Ab = sm;                    // hbar tile (built by in-kernel gather)
    uint32_t* Ah = sm + A_WORDS;          // h_old tile
    uint32_t* Bi = sm + 2 * A_WORDS;
    uint32_t sBi = smem_to_u32(Bi);

    const uint32_t* __restrict__ h_old = (layer & 1) ? g_hB : g_hA;
    uint32_t* __restrict__ h_new       = (layer & 1) ? g_hA : g_hB;

    int tid = threadIdx.x;
    int rowBase = blockIdx.x * NROW;
    int wid = tid >> 5, lane = tid & 31;

    prefetch_chunk(sBi, layer, 0, tid);   // overlaps gather + A relayout below

    // ---- Ah tile: copy h_old rows ----
    for (int i = tid; i < NROW * 16; i += 256) {
        int row = i >> 4;
        int q4  = (i & 15) * 4;
        int grr = rowBase + row;
        uint4 vh = make_uint4(0u, 0u, 0u, 0u);
        if (grr < NN) vh = *(const uint4*)(h_old + (size_t)grr * 64 + q4);
        *(uint4*)(Ah + row * TSTR + q4) = vh;
    }

    // ---- in-kernel gather: warp w builds hbar for rows w*8..w*8+7 ----
#pragma unroll
    for (int rr = 0; rr < 8; rr++) {
        int row = wid * 8 + rr;
        int grr = rowBase + row;
        float4 acc = make_float4(0.f, 0.f, 0.f, 0.f);
        int s = 0, e = 0;
        if (grr < NN) { s = g_rowptr[grr]; e = g_rowptr[grr + 1]; }
        int i = s;
        for (; i + 4 <= e; i += 4) {
            int s0 = g_srclist[i],     s1 = g_srclist[i + 1];
            int s2 = g_srclist[i + 2], s3 = g_srclist[i + 3];
            uint2 w0 = *(const uint2*)(h_old + (size_t)s0 * 64 + lane * 2);
            uint2 w1 = *(const uint2*)(h_old + (size_t)s1 * 64 + lane * 2);
            uint2 w2 = *(const uint2*)(h_old + (size_t)s2 * 64 + lane * 2);
            uint2 w3 = *(const uint2*)(h_old + (size_t)s3 * 64 + lane * 2);
            float2 a0 = __half22float2(*(__half2*)&w0.x), a1 = __half22float2(*(__half2*)&w0.y);
            float2 b0 = __half22float2(*(__half2*)&w1.x), b1 = __half22float2(*(__half2*)&w1.y);
            float2 c0 = __half22float2(*(__half2*)&w2.x), c1 = __half22float2(*(__half2*)&w2.y);
            float2 d0 = __half22float2(*(__half2*)&w3.x), d1 = __half22float2(*(__half2*)&w3.y);
            acc.x += (a0.x + b0.x) + (c0.x + d0.x);
            acc.y += (a0.y + b0.y) + (c0.y + d0.y);
            acc.z += (a1.x + b1.x) + (c1.x + d1.x);
            acc.w += (a1.y + b1.y) + (c1.y + d1.y);
        }
        for (; i < e; i++) {
            int s0 = g_srclist[i];
            uint2 w0 = *(const uint2*)(h_old + (size_t)s0 * 64 + lane * 2);
            float2 a0 = __half22float2(*(__half2*)&w0.x), a1 = __half22float2(*(__half2*)&w0.y);
            acc.x += a0.x;  acc.y += a0.y;  acc.z += a1.x;  acc.w += a1.y;
        }
        float sc = 1.0f / fmaxf((float)(e - s), 1.0f);
        uint2 outw;
        outw.x = pack_h2(acc.x * sc, acc.y * sc);
        outw.y = pack_h2(acc.z * sc, acc.w * sc);
        *(uint2*)(Ab + row * TSTR + lane * 2) = outw;
    }

    int gr = lane >> 2, tig = lane & 3;
    int wm = wid >> 1, wn = wid & 1;

    int lg = lane >> 3, lr = lane & 7;
    uint32_t aOff = ((uint32_t)((wm * 16 + lr + (lg & 1) * 8) * TSTR + (lg >> 1) * 4)) * 4;
    uint32_t bOff = ((uint32_t)((wn * 64 + lr + (lg >> 1) * 8) * TSTR + (lg & 1) * 4)) * 4;
    uint32_t aAb = smem_to_u32(Ab) + aOff;
    uint32_t aAh = smem_to_u32(Ah) + aOff;
    uint32_t aBi = sBi + bOff;
    uint32_t aBh = sBi + TILE_WORDS * 4 + bOff;

    float rf[8][4], zf[8][4];

#pragma unroll
    for (int chunk = 0; chunk < 3; chunk++) {
        CP_WAIT0();
        __syncthreads();   // B chunk (and chunk0: A/gather tiles) visible

        if (chunk < 2) {
            float acc[8][4];
#pragma unroll
            for (int ni = 0; ni < 8; ni++)
#pragma unroll
                for (int q = 0; q < 4; q++) acc[ni][q] = 0.f;
            gemm_frag(aAb, aBi, acc);
            gemm_frag(aAh, aBh, acc);

            __syncthreads();                       // all warps done reading B
            prefetch_chunk(sBi, layer, chunk + 1, tid);   // overlaps epilogue

#pragma unroll
            for (int ni = 0; ni < 8; ni++) {
                int cc = wn * 64 + ni * 8 + tig * 2;
#pragma unroll
                for (int q = 0; q < 4; q++) {
                    int col = chunk * 128 + cc + (q & 1);
                    float v = acc[ni][q] + bias_i[col] + bias_h[col];
                    float s = sigmoid_ap(v);
                    if (chunk == 0) rf[ni][q] = s; else zf[ni][q] = s;
                }
            }
        } else {
            // n = tanh(gi + b_i + r*(gh + b_h)) with ONE accumulator
            float acc[8][4];
#pragma unroll
            for (int ni = 0; ni < 8; ni++)
#pragma unroll
                for (int q = 0; q < 4; q++) acc[ni][q] = 0.f;
            gemm_frag(aAh, aBh, acc);
#pragma unroll
            for (int ni = 0; ni < 8; ni++) {
                int cc = wn * 64 + ni * 8 + tig * 2;
                float bh0 = bias_h[256 + cc], bh1 = bias_h[256 + cc + 1];
                acc[ni][0] = rf[ni][0] * (acc[ni][0] + bh0);
                acc[ni][1] = rf[ni][1] * (acc[ni][1] + bh1);
                acc[ni][2] = rf[ni][2] * (acc[ni][2] + bh0);
                acc[ni][3] = rf[ni][3] * (acc[ni][3] + bh1);
            }
            gemm_frag(aAb, aBi, acc);

            int lr0 = wm * 16 + gr;               // local rows
            int r0 = rowBase + lr0;
            int r1 = r0 + 8;
#pragma unroll
            for (int ni = 0; ni < 8; ni++) {
                int cc = wn * 64 + ni * 8 + tig * 2;
                int hw = cc >> 1;                  // half2 word index
                float bi0 = bias_i[256 + cc], bi1 = bias_i[256 + cc + 1];
                if (r0 < NN) {
                    float2 ho = __half22float2(*(__half2*)&Ah[lr0 * TSTR + hw]);
                    float n0 = tanh_ap(acc[ni][0] + bi0);
                    float n1 = tanh_ap(acc[ni][1] + bi1);
                    float hx = (1.0f - zf[ni][0]) * n0 + zf[ni][0] * ho.x;
                    float hy = (1.0f - zf[ni][1]) * n1 + zf[ni][1] * ho.y;
                    h_new[(size_t)r0 * 64 + hw] = pack_h2(hx, hy);
                }
                if (r1 < NN) {
                    float2 ho = __half22float2(*(__half2*)&Ah[(lr0 + 8) * TSTR + hw]);
                    float n2 = tanh_ap(acc[ni][2] + bi0);
                    float n3 = tanh_ap(acc[ni][3] + bi1);
                    float hx = (1.0f - zf[ni][2]) * n2 + zf[ni][2] * ho.x;
                    float hy = (1.0f - zf[ni][3]) * n3 + zf[ni][3] * ho.y;
                    h_new[(size_t)r1 * 64 + hw] = pack_h2(hx, hy);
                }
            }
        }
    }
}

// ================= final mean + tanh (reads final h buffer = g_hB) =================
__global__ void mean_tanh_kernel(float* __restrict__ out) {
    int gtid = blockIdx.x * blockDim.x + threadIdx.x;
    int node = gtid >> 5;
    int lane = threadIdx.x & 31;
    if (node < NN) {
        uint2 w = *(const uint2*)(g_hB + (size_t)node * 64 + lane * 2);
        float2 a = __half22float2(*(__half2*)&w.x);
        float2 b = __half22float2(*(__half2*)&w.y);
        float s = (a.x + a.y) + (b.x + b.y);
#pragma unroll
        for (int o = 16; o > 0; o >>= 1) s += __shfl_down_sync(0xffffffffu, s, o);
        if (lane == 0) out[node] = tanhf(s * (1.0f / 128.0f));
    }
}

// ================= launch =================
extern "C" void kernel_launch(void* const* d_in, const int* in_sizes, int n_in,
                              void* d_out, int out_size) {
    int ix = 0, ie = 1, iw = 2, iwih = 3, iwhh = 4, ibih = 5, ibhh = 6;
    {
        int w_seen = 0, b_seen = 0;
        for (int i = 0; i < n_in; i++) {
            long long s = in_sizes[i];
            if (s == (long long)NN * C) ix = i;
            else if (s == 2LL * NE) ie = i;
            else if (s == (long long)C3 * C) {
                if (w_seen == 0) iw = i;
                else if (w_seen == 1) iwih = i;
                else if (w_seen == 2) iwhh = i;
                w_seen++;
            } else if (s == C3) {
                if (b_seen == 0) ibih = i;
                else if (b_seen == 1) ibhh = i;
                b_seen++;
            }
        }
    }
    const float* x      = (const float*)d_in[ix];
    const void*  ei     = d_in[ie];
    const float* weight = (const float*)d_in[iw];
    const float* w_ih   = (const float*)d_in[iwih];
    const float* w_hh   = (const float*)d_in[iwhh];
    const float* b_ih   = (const float*)d_in[ibih];
    const float* b_hh   = (const float*)d_in[ibhh];
    float*       out    = (float*)d_out;

    static bool attr_set = false;
    if (!attr_set) {
        cudaFuncSetAttribute(fused_kernel, cudaFuncAttributeMaxDynamicSharedMemorySize, FUSED_SMEM);
        attr_set = true;
    }

    zero_deg_kernel<<<(NN + 255) / 256, 256>>>();
    prep1_kernel<<<NB_COUNT + NB_INIT + NB_WF, 256>>>(ei, x, weight, w_ih);
    scanA_kernel<<<SCAN_NB, SCAN_B>>>();
    scanB_kernel<<<1, 256>>>();
    scanC_kernel<<<SCAN_NB, SCAN_B>>>();
    prep2_kernel<<<NB_FILL + NB_PREPB, 256>>>(ei, w_hh);

    int fused_blocks = (NN + NROW - 1) / NROW;   // 1563

    for (int l = 0; l < NLAYERS; l++)
        fused_kernel<<<fused_blocks, 256, FUSED_SMEM>>>(l, b_ih, b_hh);

    mean_tanh_kernel<<<(NN * 32 + 255) / 256, 256>>>(out);
}

// round 15
// speedup vs baseline: 1.3303x; 1.3303x over previous
#include <cuda_runtime.h>
#include <cuda_fp16.h>
#include <cstdint>

#define NN 100000
#define NE 1600000
#define C 128
#define C3 384
#define NLAYERS 3
#define SCAN_B 512
#define SCAN_NB ((NN + SCAN_B - 1) / SCAN_B)   // 196

// padded tile layout: [rows][68 uint32 words] (64 used = 128 fp16, +4 pad)
#define TSTR 68
#define TILE_WORDS (128 * TSTR)       // B tiles: 128 n-rows  (34816 B)
#define NROW 64                       // fused-kernel CTA rows
#define A_WORDS (NROW * TSTR)         // A tiles: 64 rows     (17408 B)

// P1 role grid split
#define NB_COUNT 6250
#define NB_INIT  25000
#define NB_WF    576
// P2 role grid split
#define NB_FILL  6250
#define NB_PREPB 384

// ================= scratch (device globals; no allocation allowed) =================
__device__ __align__(256) uint32_t g_h16[NN * 64];       // hidden state (fp16 half2 words)
__device__ __align__(256) uint32_t g_hbar16[NN * 64];    // fp16 mean-pooled neighbor h
__device__ __align__(256) float    g_wfused[3 * 128 * 384];  // W_l @ w_ih^T (fp32)
// fp16 padded B tiles: 0-8 = Wfused (layer*3+chunk), 9-11 = w_hh chunks
__device__ __align__(256) uint32_t g_btile[12 * TILE_WORDS];
// CSR build
__device__ __align__(256) int g_deg[NN];
__device__ __align__(256) int g_bsum[SCAN_NB];
__device__ __align__(256) int g_rowptr[NN + 1];
__device__ __align__(256) int g_cur[NN];
__device__ __align__(256) int g_srclist[NE];

// ================= helpers =================
__device__ __forceinline__ uint32_t smem_to_u32(const void* p) {
    uint32_t a;
    asm("{ .reg .u64 t; cvta.to.shared.u64 t, %1; cvt.u32.u64 %0, t; }" : "=r"(a) : "l"(p));
    return a;
}
__device__ __forceinline__ void cp_async16(uint32_t saddr, const void* gaddr) {
    asm volatile("cp.async.cg.shared.global [%0], [%1], 16;" :: "r"(saddr), "l"(gaddr));
}
#define CP_COMMIT() asm volatile("cp.async.commit_group;" ::: "memory")
#define CP_WAIT0()  asm volatile("cp.async.wait_group 0;" ::: "memory")

__device__ __forceinline__ uint32_t pack_h2(float a, float b) {
    __half2 h = __floats2half2_rn(a, b);
    return *(uint32_t*)&h;
}
__device__ __forceinline__ void ldmx4(uint32_t* r, uint32_t saddr) {
    asm volatile("ldmatrix.sync.aligned.m8n8.x4.shared.b16 {%0,%1,%2,%3}, [%4];"
                 : "=r"(r[0]), "=r"(r[1]), "=r"(r[2]), "=r"(r[3]) : "r"(saddr));
}
__device__ __forceinline__ float tanh_ap(float x) {
    float y;
    asm("tanh.approx.f32 %0, %1;" : "=f"(y) : "f"(x));
    return y;
}
__device__ __forceinline__ float sigmoid_ap(float x) {
    return fmaf(tanh_ap(0.5f * x), 0.5f, 0.5f);
}

// per-block edge dtype detection (thread 0 + smem broadcast)
__device__ __forceinline__ int detect_block(const unsigned int* ei32, int* s_flag) {
    if (threadIdx.x == 0) {
        int is64 = 1;
        for (int i = 1; i < 64; i += 2)
            if (ei32[i] != 0u) { is64 = 0; break; }
        *s_flag = is64;
    }
    __syncthreads();
    return *s_flag;
}
__device__ __forceinline__ int load_edge_f(const void* ei, long long idx, int is64) {
    int v;
    if (is64) v = (int)((const long long*)ei)[idx];
    else      v = ((const int*)ei)[idx];
    return min(max(v, 0), NN - 1);
}

// ================= P0: zero degree array =================
__global__ void zero_deg_kernel() {
    int i = blockIdx.x * blockDim.x + threadIdx.x;
    if (i < NN) g_deg[i] = 0;
}

// ================= P1: count + init_h + wfused (one grid, role by block) =========
__global__ void prep1_kernel(const void* __restrict__ ei, const float* __restrict__ x,
                             const float* __restrict__ weight, const float* __restrict__ w_ih) {
    __shared__ int s_flag;
    int b = blockIdx.x;
    if (b < NB_COUNT) {
        int is64 = detect_block((const unsigned int*)ei, &s_flag);
        int e = b * 256 + threadIdx.x;
        if (e < NE) atomicAdd(&g_deg[load_edge_f(ei, (long long)NE + e, is64)], 1);
    } else if (b < NB_COUNT + NB_INIT) {
        int i = (b - NB_COUNT) * 256 + threadIdx.x;
        if (i < NN * 64) {
            float2 v = ((const float2*)x)[i];
            g_h16[i] = pack_h2(v.x, v.y);
        }
    } else {
        int idx = (b - NB_COUNT - NB_INIT) * 256 + threadIdx.x;
        if (idx < 3 * 128 * 384) {
            int l = idx / 49152;
            int rem = idx % 49152;
            int k = rem / 384;
            int n = rem % 384;
            const float* wl = weight + l * 16384 + k * 128;
            const float* wr = w_ih + (size_t)n * 128;
            float s = 0.f;
#pragma unroll 8
            for (int j = 0; j < 128; j++) s += wl[j] * wr[j];
            g_wfused[idx] = s;
        }
    }
}

// ================= scans =================
__global__ void scanA_kernel() {
    __shared__ int sh[SCAN_B];
    int i = blockIdx.x * SCAN_B + threadIdx.x;
    sh[threadIdx.x] = (i < NN) ? g_deg[i] : 0;
    __syncthreads();
    for (int off = SCAN_B / 2; off > 0; off >>= 1) {
        if (threadIdx.x < off) sh[threadIdx.x] += sh[threadIdx.x + off];
        __syncthreads();
    }
    if (threadIdx.x == 0) g_bsum[blockIdx.x] = sh[0];
}
__global__ void scanB_kernel() {      // parallel exclusive scan of 196 block sums
    __shared__ int sh[256];
    int t = threadIdx.x;
    int v = (t < SCAN_NB) ? g_bsum[t] : 0;
    sh[t] = v;
    __syncthreads();
    for (int off = 1; off < 256; off <<= 1) {
        int tv = (t >= off) ? sh[t - off] : 0;
        __syncthreads();
        sh[t] += tv;
        __syncthreads();
    }
    if (t < SCAN_NB) g_bsum[t] = sh[t] - v;   // inclusive -> exclusive
}
__global__ void scanC_kernel() {
    __shared__ int sh[SCAN_B];
    int i = blockIdx.x * SCAN_B + threadIdx.x;
    int v = (i < NN) ? g_deg[i] : 0;
    sh[threadIdx.x] = v;
    __syncthreads();
    for (int off = 1; off < SCAN_B; off <<= 1) {
        int t = (threadIdx.x >= off) ? sh[threadIdx.x - off] : 0;
        __syncthreads();
        sh[threadIdx.x] += t;
        __syncthreads();
    }
    if (i < NN) {
        int excl = sh[threadIdx.x] - v + g_bsum[blockIdx.x];
        g_rowptr[i] = excl;
        g_cur[i] = excl;
    }
    if (i == NN - 1) g_rowptr[NN] = NE;
}

// ================= P2: fill + prep_btiles (one grid) =================
__global__ void prep2_kernel(const void* __restrict__ ei, const float* __restrict__ w_hh) {
    __shared__ int s_flag;
    int b = blockIdx.x;
    if (b < NB_FILL) {
        int is64 = detect_block((const unsigned int*)ei, &s_flag);
        int e = b * 256 + threadIdx.x;
        if (e < NE) {
            int src = load_edge_f(ei, e, is64);
            int dst = load_edge_f(ei, (long long)NE + e, is64);
            int pos = atomicAdd(&g_cur[dst], 1);
            if (pos >= 0 && pos < NE) g_srclist[pos] = src;
        }
    } else {
        int idx = (b - NB_FILL) * 256 + threadIdx.x;
        if (idx < 12 * 128 * 64) {
            int tile = idx >> 13;
            int rem  = idx & 8191;
            int n  = rem >> 6;
            int k2 = rem & 63;
            float v0, v1;
            if (tile < 9) {
                int l = tile / 3, chunk = tile % 3;
                const float* base = g_wfused + l * 49152 + chunk * 128 + n;
                v0 = base[(k2 * 2) * 384];
                v1 = base[(k2 * 2 + 1) * 384];
            } else {
                const float* r = w_hh + ((size_t)((tile - 9) * 128 + n)) * 128;
                v0 = r[k2 * 2];  v1 = r[k2 * 2 + 1];
            }
            g_btile[(size_t)tile * TILE_WORDS + n * TSTR + k2] = pack_h2(v0, v1);
        }
    }
}

// ================= gather: hbar16 = mean of h16; HALF-WARP per node, uint4 loads ====
__global__ void gather_kernel() {
    int gtid = blockIdx.x * blockDim.x + threadIdx.x;
    int node = gtid >> 4;            // one node per 16 lanes
    int l16  = threadIdx.x & 15;     // lane within half-warp: 16B each -> 256B row
    if (node >= NN) return;
    int s = g_rowptr[node];
    int e = g_rowptr[node + 1];
    float4 aLo = make_float4(0.f, 0.f, 0.f, 0.f);
    float4 aHi = make_float4(0.f, 0.f, 0.f, 0.f);
    int i = s;
    for (; i + 2 <= e; i += 2) {
        int s0 = g_srclist[i];
        int s1 = g_srclist[i + 1];
        uint4 w0 = *(const uint4*)(g_h16 + (size_t)s0 * 64 + l16 * 4);
        uint4 w1 = *(const uint4*)(g_h16 + (size_t)s1 * 64 + l16 * 4);
        float2 p0 = __half22float2(*(__half2*)&w0.x), q0 = __half22float2(*(__half2*)&w1.x);
        float2 p1 = __half22float2(*(__half2*)&w0.y), q1 = __half22float2(*(__half2*)&w1.y);
        float2 p2 = __half22float2(*(__half2*)&w0.z), q2 = __half22float2(*(__half2*)&w1.z);
        float2 p3 = __half22float2(*(__half2*)&w0.w), q3 = __half22float2(*(__half2*)&w1.w);
        aLo.x += p0.x + q0.x;  aLo.y += p0.y + q0.y;
        aLo.z += p1.x + q1.x;  aLo.w += p1.y + q1.y;
        aHi.x += p2.x + q2.x;  aHi.y += p2.y + q2.y;
        aHi.z += p3.x + q3.x;  aHi.w += p3.y + q3.y;
    }
    if (i < e) {
        int s0 = g_srclist[i];
        uint4 w0 = *(const uint4*)(g_h16 + (size_t)s0 * 64 + l16 * 4);
        float2 p0 = __half22float2(*(__half2*)&w0.x);
        float2 p1 = __half22float2(*(__half2*)&w0.y);
        float2 p2 = __half22float2(*(__half2*)&w0.z);
        float2 p3 = __half22float2(*(__half2*)&w0.w);
        aLo.x += p0.x;  aLo.y += p0.y;  aLo.z += p1.x;  aLo.w += p1.y;
        aHi.x += p2.x;  aHi.y += p2.y;  aHi.z += p3.x;  aHi.w += p3.y;
    }
    float sc = 1.0f / fmaxf((float)(e - s), 1.0f);
    uint4 outw;
    outw.x = pack_h2(aLo.x * sc, aLo.y * sc);
    outw.y = pack_h2(aLo.z * sc, aLo.w * sc);
    outw.z = pack_h2(aHi.x * sc, aHi.y * sc);
    outw.w = pack_h2(aHi.z * sc, aHi.w * sc);
    *(uint4*)(g_hbar16 + (size_t)node * 64 + l16 * 4) = outw;
}

// ================= mma.sync m16n8k16 fp16 =================
__device__ __forceinline__ void mma16816(float* c, const uint32_t* a, const uint32_t* b) {
    asm volatile(
        "mma.sync.aligned.m16n8k16.row.col.f32.f16.f16.f32 "
        "{%0,%1,%2,%3}, {%4,%5,%6,%7}, {%8,%9}, {%0,%1,%2,%3};"
        : "+f"(c[0]), "+f"(c[1]), "+f"(c[2]), "+f"(c[3])
        : "r"(a[0]), "r"(a[1]), "r"(a[2]), "r"(a[3]), "r"(b[0]), "r"(b[1]));
}

__device__ __forceinline__ void gemm_frag(uint32_t aAddr, uint32_t bAddr, float acc[8][4]) {
#pragma unroll
    for (int ks = 0; ks < 8; ks++) {
        uint32_t a[4];
        ldmx4(a, aAddr + ks * 32);
#pragma unroll
        for (int p = 0; p < 4; p++) {
            uint32_t b[4];
            ldmx4(b, bAddr + p * (16 * TSTR * 4) + ks * 32);
            mma16816(acc[2 * p],     a, b);
            mma16816(acc[2 * p + 1], a, b + 2);
        }
    }
}

// ================= fused gi-GEMM + gh-GEMM + GRU gate =================
#define FUSED_SMEM ((2 * A_WORDS + 2 * TILE_WORDS) * 4)   // 104448 B, 2 CTAs/SM

__device__ __forceinline__ void prefetch_chunk(uint32_t sB, int layer, int chunk, int tid) {
    const uint32_t* srcI = g_btile + (size_t)(layer * 3 + chunk) * TILE_WORDS;
    const uint32_t* srcH = g_btile + (size_t)(9 + chunk) * TILE_WORDS;
    for (int i = tid * 4; i < TILE_WORDS; i += 256 * 4) {
        cp_async16(sB + i * 4, srcI + i);
        cp_async16(sB + (TILE_WORDS + i) * 4, srcH + i);
    }
    CP_COMMIT();
}

__global__ void __launch_bounds__(256, 2)
fused_kernel(int layer, const float* __restrict__ bias_i, const float* __restrict__ bias_h)
{
    extern __shared__ uint32_t sm[];
    uint32_t* Ab = sm;
    uint32_t* Ah = sm + A_WORDS;
    uint32_t* Bi = sm + 2 * A_WORDS;
    uint32_t sBi = smem_to_u32(Bi);

    int tid = threadIdx.x;
    int rowBase = blockIdx.x * NROW;

    prefetch_chunk(sBi, layer, 0, tid);   // overlaps with A relayout

    // ---- A tiles: relayout fp16 hbar/h into padded smem ----
    for (int i = tid; i < NROW * 16; i += 256) {
        int row = i >> 4;
        int q4  = (i & 15) * 4;
        int grr = rowBase + row;
        uint4 vb = make_uint4(0u, 0u, 0u, 0u);
        uint4 vh = make_uint4(0u, 0u, 0u, 0u);
        if (grr < NN) {
            vb = *(const uint4*)(g_hbar16 + (size_t)grr * 64 + q4);
            vh = *(const uint4*)(g_h16   + (size_t)grr * 64 + q4);
        }
        int o = row * TSTR + q4;
        *(uint4*)(Ab + o) = vb;
        *(uint4*)(Ah + o) = vh;
    }

    int wid = tid >> 5, lane = tid & 31;
    int gr = lane >> 2, tig = lane & 3;
    int wm = wid >> 1, wn = wid & 1;

    int lg = lane >> 3, lr = lane & 7;
    uint32_t aOff = ((uint32_t)((wm * 16 + lr + (lg & 1) * 8) * TSTR + (lg >> 1) * 4)) * 4;
    uint32_t bOff = ((uint32_t)((wn * 64 + lr + (lg >> 1) * 8) * TSTR + (lg & 1) * 4)) * 4;
    uint32_t aAb = smem_to_u32(Ab) + aOff;
    uint32_t aAh = smem_to_u32(Ah) + aOff;
    uint32_t aBi = sBi + bOff;
    uint32_t aBh = sBi + TILE_WORDS * 4 + bOff;

    float rf[8][4], zf[8][4];

#pragma unroll
    for (int chunk = 0; chunk < 3; chunk++) {
        CP_WAIT0();
        __syncthreads();   // B chunk (and chunk0: A tiles) visible to all warps

        if (chunk < 2) {
            float acc[8][4];
#pragma unroll
            for (int ni = 0; ni < 8; ni++)
#pragma unroll
                for (int q = 0; q < 4; q++) acc[ni][q] = 0.f;
            gemm_frag(aAb, aBi, acc);
            gemm_frag(aAh, aBh, acc);

            __syncthreads();                       // all warps done reading B
            prefetch_chunk(sBi, layer, chunk + 1, tid);   // overlaps epilogue below

#pragma unroll
            for (int ni = 0; ni < 8; ni++) {
                int cc = wn * 64 + ni * 8 + tig * 2;
#pragma unroll
                for (int q = 0; q < 4; q++) {
                    int col = chunk * 128 + cc + (q & 1);
                    float v = acc[ni][q] + bias_i[col] + bias_h[col];
                    float s = sigmoid_ap(v);
                    if (chunk == 0) rf[ni][q] = s; else zf[ni][q] = s;
                }
            }
        } else {
            // n = tanh(gi + b_i + r*(gh + b_h)) with ONE accumulator
            float acc[8][4];
#pragma unroll
            for (int ni = 0; ni < 8; ni++)
#pragma unroll
                for (int q = 0; q < 4; q++) acc[ni][q] = 0.f;
            gemm_frag(aAh, aBh, acc);
#pragma unroll
            for (int ni = 0; ni < 8; ni++) {
                int cc = wn * 64 + ni * 8 + tig * 2;
                float bh0 = bias_h[256 + cc], bh1 = bias_h[256 + cc + 1];
                acc[ni][0] = rf[ni][0] * (acc[ni][0] + bh0);
                acc[ni][1] = rf[ni][1] * (acc[ni][1] + bh1);
                acc[ni][2] = rf[ni][2] * (acc[ni][2] + bh0);
                acc[ni][3] = rf[ni][3] * (acc[ni][3] + bh1);
            }
            gemm_frag(aAb, aBi, acc);

            int lr0 = wm * 16 + gr;               // local rows
            int r0 = rowBase + lr0;
            int r1 = r0 + 8;
#pragma unroll
            for (int ni = 0; ni < 8; ni++) {
                int cc = wn * 64 + ni * 8 + tig * 2;
                int hw = cc >> 1;                  // half2 word index
                float bi0 = bias_i[256 + cc], bi1 = bias_i[256 + cc + 1];
                if (r0 < NN) {
                    float2 ho = __half22float2(*(__half2*)&Ah[lr0 * TSTR + hw]);
                    float n0 = tanh_ap(acc[ni][0] + bi0);
                    float n1 = tanh_ap(acc[ni][1] + bi1);
                    float hx = (1.0f - zf[ni][0]) * n0 + zf[ni][0] * ho.x;
                    float hy = (1.0f - zf[ni][1]) * n1 + zf[ni][1] * ho.y;
                    g_h16[(size_t)r0 * 64 + hw] = pack_h2(hx, hy);
                }
                if (r1 < NN) {
                    float2 ho = __half22float2(*(__half2*)&Ah[(lr0 + 8) * TSTR + hw]);
                    float n2 = tanh_ap(acc[ni][2] + bi0);
                    float n3 = tanh_ap(acc[ni][3] + bi1);
                    float hx = (1.0f - zf[ni][2]) * n2 + zf[ni][2] * ho.x;
                    float hy = (1.0f - zf[ni][3]) * n3 + zf[ni][3] * ho.y;
                    g_h16[(size_t)r1 * 64 + hw] = pack_h2(hx, hy);
                }
            }
        }
    }
}

// ================= final mean + tanh (reads h16) =================
__global__ void mean_tanh_kernel(float* __restrict__ out) {
    int gtid = blockIdx.x * blockDim.x + threadIdx.x;
    int node = gtid >> 5;
    int lane = threadIdx.x & 31;
    if (node < NN) {
        uint2 w = *(const uint2*)(g_h16 + (size_t)node * 64 + lane * 2);
        float2 a = __half22float2(*(__half2*)&w.x);
        float2 b = __half22float2(*(__half2*)&w.y);
        float s = (a.x + a.y) + (b.x + b.y);
#pragma unroll
        for (int o = 16; o > 0; o >>= 1) s += __shfl_down_sync(0xffffffffu, s, o);
        if (lane == 0) out[node] = tanhf(s * (1.0f / 128.0f));
    }
}

// ================= launch =================
extern "C" void kernel_launch(void* const* d_in, const int* in_sizes, int n_in,
                              void* d_out, int out_size) {
    int ix = 0, ie = 1, iw = 2, iwih = 3, iwhh = 4, ibih = 5, ibhh = 6;
    {
        int w_seen = 0, b_seen = 0;
        for (int i = 0; i < n_in; i++) {
            long long s = in_sizes[i];
            if (s == (long long)NN * C) ix = i;
            else if (s == 2LL * NE) ie = i;
            else if (s == (long long)C3 * C) {
                if (w_seen == 0) iw = i;
                else if (w_seen == 1) iwih = i;
                else if (w_seen == 2) iwhh = i;
                w_seen++;
            } else if (s == C3) {
                if (b_seen == 0) ibih = i;
                else if (b_seen == 1) ibhh = i;
                b_seen++;
            }
        }
    }
    const float* x      = (const float*)d_in[ix];
    const void*  ei     = d_in[ie];
    const float* weight = (const float*)d_in[iw];
    const float* w_ih   = (const float*)d_in[iwih];
    const float* w_hh   = (const float*)d_in[iwhh];
    const float* b_ih   = (const float*)d_in[ibih];
    const float* b_hh   = (const float*)d_in[ibhh];
    float*       out    = (float*)d_out;

    static bool attr_set = false;
    if (!attr_set) {
        cudaFuncSetAttribute(fused_kernel, cudaFuncAttributeMaxDynamicSharedMemorySize, FUSED_SMEM);
        attr_set = true;
    }

    zero_deg_kernel<<<(NN + 255) / 256, 256>>>();
    prep1_kernel<<<NB_COUNT + NB_INIT + NB_WF, 256>>>(ei, x, weight, w_ih);
    scanA_kernel<<<SCAN_NB, SCAN_B>>>();
    scanB_kernel<<<1, 256>>>();
    scanC_kernel<<<SCAN_NB, SCAN_B>>>();
    prep2_kernel<<<NB_FILL + NB_PREPB, 256>>>(ei, w_hh);

    int gather_blocks = (NN * 16 + 255) / 256;   // half-warp per node
    int fused_blocks = (NN + NROW - 1) / NROW;   // 1563

    for (int l = 0; l < NLAYERS; l++) {
        gather_kernel<<<gather_blocks, 256>>>();
        fused_kernel<<<fused_blocks, 256, FUSED_SMEM>>>(l, b_ih, b_hh);
    }

    mean_tanh_kernel<<<(NN * 32 + 255) / 256, 256>>>(out);
}